// round 13
// baseline (speedup 1.0000x reference)
#include <cuda_runtime.h>
#include <cuda_bf16.h>
#include <math.h>

#define DEG2RAD 0.017453292519943295f
#define LOG_SMIN -2.995732273553991f   // log(0.05)

#define BLOCK 128
#define MPB   (2 * BLOCK)   // matrices per block

typedef unsigned long long u64;
struct f2 { u64 v; };

__device__ __forceinline__ f2 mk2(float lo, float hi) {
    f2 r; asm("mov.b64 %0, {%1, %2};" : "=l"(r.v) : "f"(lo), "f"(hi)); return r;
}
__device__ __forceinline__ f2 bc2(float x) { return mk2(x, x); }
__device__ __forceinline__ void un2(f2 a, float &lo, float &hi) {
    asm("mov.b64 {%0, %1}, %2;" : "=f"(lo), "=f"(hi) : "l"(a.v));
}
__device__ __forceinline__ f2 add2(f2 a, f2 b) {
    f2 r; asm("add.rn.f32x2 %0, %1, %2;" : "=l"(r.v) : "l"(a.v), "l"(b.v)); return r;
}
__device__ __forceinline__ f2 mul2(f2 a, f2 b) {
    f2 r; asm("mul.rn.f32x2 %0, %1, %2;" : "=l"(r.v) : "l"(a.v), "l"(b.v)); return r;
}
__device__ __forceinline__ f2 fma2(f2 a, f2 b, f2 c) {
    f2 r; asm("fma.rn.f32x2 %0, %1, %2, %3;" : "=l"(r.v) : "l"(a.v), "l"(b.v), "l"(c.v)); return r;
}
__device__ __forceinline__ f2 neg2(f2 a) {
    f2 r; u64 m = 0x8000000080000000ULL;
    asm("xor.b64 %0, %1, %2;" : "=l"(r.v) : "l"(a.v), "l"(m)); return r;
}
__device__ __forceinline__ f2 abs2(f2 a) {
    f2 r; u64 m = 0x7fffffff7fffffffULL;
    asm("and.b64 %0, %1, %2;" : "=l"(r.v) : "l"(a.v), "l"(m)); return r;
}
__device__ __forceinline__ f2 sgn2(f2 a) {   // sign bits only
    f2 r; u64 m = 0x8000000080000000ULL;
    asm("and.b64 %0, %1, %2;" : "=l"(r.v) : "l"(a.v), "l"(m)); return r;
}
__device__ __forceinline__ f2 xor2(f2 a, f2 b) {
    f2 r; asm("xor.b64 %0, %1, %2;" : "=l"(r.v) : "l"(a.v), "l"(b.v)); return r;
}

// Full Jacobi step, branch-free exact rotation, NO-SWAP convention.
// Roles: s11=S_pp, s21=S_qp (annihilated, NOT written), s22=S_qq,
//        s31=S_tp, s32=S_tq. V cols (va,vb) = (p,q).
template <bool S31_ZERO>
__device__ __forceinline__ void jx(
    f2 &s11, f2 &s21, f2 &s22, f2 &s31, f2 &s32,
    f2 &va1, f2 &va2, f2 &va3,
    f2 &vb1, f2 &vb2, f2 &vb3)
{
    const f2 HALF = bc2(0.5f);
    const f2 CM1  = bc2(-1.0f);
    const f2 EPS  = bc2(1e-28f);

    f2 d  = fma2(s22, CM1, s11);
    f2 ad = abs2(d);
    f2 sg = sgn2(d);
    f2 ts = add2(s21, s21);
    f2 r2 = fma2(d, d, fma2(ts, ts, EPS));

    float r2l, r2h; un2(r2, r2l, r2h);
    f2 w = mk2(rsqrtf(r2l), rsqrtf(r2h));

    f2 c2t = mul2(ad, w);
    f2 a2  = fma2(c2t, HALF, HALF);
    float a2l, a2h; un2(a2, a2l, a2h);
    f2 ia = mk2(rsqrtf(a2l), rsqrtf(a2h));
    f2 aa = mul2(a2, ia);
    f2 bb = mul2(mul2(xor2(s21, sg), w), ia);

    // diagonal, closed form: s11' = m + sign(d)*r/2
    f2 rh  = mul2(mul2(r2, w), HALF);
    f2 rhs = xor2(rh, sg);
    f2 m   = mul2(add2(s11, s22), HALF);
    s11 = add2(m, rhs);
    s22 = add2(m, neg2(rhs));

    // third row/col rotate
    f2 nbb = neg2(bb);
    if (S31_ZERO) {
        f2 o32 = mul2(aa, s32);
        s31 = mul2(bb, s32);
        s32 = o32;
    } else {
        f2 o31 = fma2(aa, s31, mul2(bb, s32));
        f2 o32 = fma2(nbb, s31, mul2(aa, s32));
        s31 = o31; s32 = o32;
    }

    // V column rotate
    f2 t;
    t = fma2(aa, va1, mul2(bb, vb1)); vb1 = fma2(nbb, va1, mul2(aa, vb1)); va1 = t;
    t = fma2(aa, va2, mul2(bb, vb2)); vb2 = fma2(nbb, va2, mul2(aa, vb2)); va2 = t;
    t = fma2(aa, va3, mul2(bb, vb3)); vb3 = fma2(nbb, va3, mul2(aa, vb3)); va3 = t;
}

// FINAL Jacobi step: V columns + diagonal refresh (third-pair S skipped).
// Diagonal kept because eps_j is computed from the converged diagonal.
__device__ __forceinline__ void jxD(
    f2 &s11, f2 s21, f2 &s22,
    f2 &va1, f2 &va2, f2 &va3,
    f2 &vb1, f2 &vb2, f2 &vb3)
{
    const f2 HALF = bc2(0.5f);
    const f2 CM1  = bc2(-1.0f);
    const f2 EPS  = bc2(1e-28f);

    f2 d  = fma2(s22, CM1, s11);
    f2 ad = abs2(d);
    f2 sg = sgn2(d);
    f2 ts = add2(s21, s21);
    f2 r2 = fma2(d, d, fma2(ts, ts, EPS));

    float r2l, r2h; un2(r2, r2l, r2h);
    f2 w = mk2(rsqrtf(r2l), rsqrtf(r2h));

    f2 c2t = mul2(ad, w);
    f2 a2  = fma2(c2t, HALF, HALF);
    float a2l, a2h; un2(a2, a2l, a2h);
    f2 ia = mk2(rsqrtf(a2l), rsqrtf(a2h));
    f2 aa = mul2(a2, ia);
    f2 bb = mul2(mul2(xor2(s21, sg), w), ia);
    f2 nbb = neg2(bb);

    // diagonal refresh
    f2 rh  = mul2(mul2(r2, w), HALF);
    f2 rhs = xor2(rh, sg);
    f2 m   = mul2(add2(s11, s22), HALF);
    s11 = add2(m, rhs);
    s22 = add2(m, neg2(rhs));

    f2 t;
    t = fma2(aa, va1, mul2(bb, vb1)); vb1 = fma2(nbb, va1, mul2(aa, vb1)); va1 = t;
    t = fma2(aa, va2, mul2(bb, vb2)); vb2 = fma2(nbb, va2, mul2(aa, vb2)); va2 = t;
    t = fma2(aa, va3, mul2(bb, vb3)); vb3 = fma2(nbb, va3, mul2(aa, vb3)); va3 = t;
}

__global__ void __launch_bounds__(BLOCK, 7)
dp_plasticity_kernel(const float* __restrict__ F,
                     const float* __restrict__ ylog_p,
                     const float* __restrict__ nu_p,
                     const float* __restrict__ phi_p,
                     const float* __restrict__ coh_p,
                     float* __restrict__ out, int n) {
    __shared__ float sm[MPB * 9];

    const int tid  = threadIdx.x;
    const int base = blockIdx.x * MPB;
    const int cnt  = min(MPB, n - base);
    const int nflt = cnt * 9;

    // ---- coalesced load: global -> smem (linear layout) ----
    if (cnt == MPB) {
        const float4* gv = (const float4*)(F + (size_t)base * 9);
        float4* sv = (float4*)sm;
        #pragma unroll
        for (int k = tid; k < MPB * 9 / 4; k += BLOCK) sv[k] = gv[k];
    } else {
        const float* g = F + (size_t)base * 9;
        for (int k = tid; k < nflt; k += BLOCK) sm[k] = g[k];
        for (int k = nflt + tid; k < MPB * 9; k += BLOCK) sm[k] = 1.0f;
    }
    __syncthreads();

    {
        const float* A0 = sm + tid * 9;
        const float* A1 = sm + (tid + BLOCK) * 9;
        f2 a11 = mk2(A0[0], A1[0]);
        f2 a12 = mk2(A0[1], A1[1]);
        f2 a13 = mk2(A0[2], A1[2]);
        f2 a21 = mk2(A0[3], A1[3]);
        f2 a22 = mk2(A0[4], A1[4]);
        f2 a23 = mk2(A0[5], A1[5]);
        f2 a31 = mk2(A0[6], A1[6]);
        f2 a32 = mk2(A0[7], A1[7]);
        f2 a33 = mk2(A0[8], A1[8]);

        // ---- S = A^T A ----
        f2 s11 = fma2(a11, a11, fma2(a21, a21, mul2(a31, a31)));
        f2 s21 = fma2(a11, a12, fma2(a21, a22, mul2(a31, a32)));
        f2 s22 = fma2(a12, a12, fma2(a22, a22, mul2(a32, a32)));
        f2 s31 = fma2(a11, a13, fma2(a21, a23, mul2(a31, a33)));
        f2 s32 = fma2(a12, a13, fma2(a22, a23, mul2(a32, a33)));
        f2 s33 = fma2(a13, a13, fma2(a23, a23, mul2(a33, a33)));

        // ---- V = I ----
        f2 v11 = bc2(1.0f), v12 = bc2(0.0f), v13 = bc2(0.0f);
        f2 v21 = bc2(0.0f), v22 = bc2(1.0f), v23 = bc2(0.0f);
        f2 v31 = bc2(0.0f), v32 = bc2(0.0f), v33 = bc2(1.0f);

        // ---- exact cyclic Jacobi, 8 rotations (last: V + diagonal only) ----
        jx<false>(s11, s21, s22, s31, s32, v11, v21, v31, v12, v22, v32);
        jx<true >(s22, s32, s33, s21, s31, v12, v22, v32, v13, v23, v33);
        jx<true >(s33, s31, s11, s32, s21, v13, v23, v33, v11, v21, v31);
        jx<true >(s11, s21, s22, s31, s32, v11, v21, v31, v12, v22, v32);
        jx<true >(s22, s32, s33, s21, s31, v12, v22, v32, v13, v23, v33);
        jx<true >(s33, s31, s11, s32, s21, v13, v23, v33, v11, v21, v31);
        jx<true >(s11, s21, s22, s31, s32, v11, v21, v31, v12, v22, v32);
        jxD(s22, s32, s33, v12, v22, v32, v13, v23, v33);
        // eigenvalues (to ~1e-5 rel): lam1=s11, lam2=s22, lam3=s33;
        // columns of V correspond 1,2,3.

        // ---- material params (uniform scalars) ----
        float ylog = __ldg(ylog_p);
        float nu   = __ldg(nu_p);
        float phi  = __ldg(phi_p);
        float coh  = __ldg(coh_p);
        float E = __expf(ylog);
        float sinphi = __sinf(phi * DEG2RAD);
        float alpha = sqrtf(2.0f / 3.0f) * 2.0f * sinphi / (3.0f - sinphi);
        float mu = E / (2.0f * (1.0f + nu));
        float la = E * nu / ((1.0f + nu) * (1.0f - 2.0f * nu));
        float coef = (3.0f * la + 2.0f * mu) / (2.0f * mu) * alpha;

        // ---- return map from the DIAGONAL eigenvalues (clamped -> bounded
        //      error ~1e-5 typical; independent of B/rho -> overlaps them) ----
        float l1l, l1h, l2l, l2h, l3l, l3h;
        un2(s11, l1l, l1h); un2(s22, l2l, l2h); un2(s33, l3l, l3h);
        float e1l = fmaxf(0.5f * __logf(fmaxf(l1l, 1e-30f)), LOG_SMIN);
        float e1h = fmaxf(0.5f * __logf(fmaxf(l1h, 1e-30f)), LOG_SMIN);
        float e2l = fmaxf(0.5f * __logf(fmaxf(l2l, 1e-30f)), LOG_SMIN);
        float e2h = fmaxf(0.5f * __logf(fmaxf(l2h, 1e-30f)), LOG_SMIN);
        float e3l = fmaxf(0.5f * __logf(fmaxf(l3l, 1e-30f)), LOG_SMIN);
        float e3h = fmaxf(0.5f * __logf(fmaxf(l3h, 1e-30f)), LOG_SMIN);

        f2 e1 = mk2(e1l, e1h), e2 = mk2(e2l, e2h), e3 = mk2(e3l, e3h);
        f2 tr = add2(e1, add2(e2, e3));
        f2 nm = mul2(tr, bc2(-1.0f / 3.0f));
        f2 h1 = add2(e1, nm), h2 = add2(e2, nm), h3 = add2(e3, nm);
        f2 nrm2 = fma2(h1, h1, fma2(h2, h2, mul2(h3, h3)));

        float n2l, n2h; un2(nrm2, n2l, n2h);
        n2l = fmaxf(n2l, 1e-20f); n2h = fmaxf(n2h, 1e-20f);
        float rnl = rsqrtf(n2l), rnh = rsqrtf(n2h);
        float nrml = n2l * rnl, nrmh = n2h * rnh;

        f2 st = add2(tr, bc2(-3.0f * coh));
        float stl, sth; un2(st, stl, sth);
        float kl = fmaxf(nrml + coef * stl, 0.0f) * rnl;
        float kh = fmaxf(nrmh + coef * sth, 0.0f) * rnh;
        f2 nk = mk2(-kl, -kh);
        f2 ce1 = fma2(nk, h1, e1);
        f2 ce2 = fma2(nk, h2, e2);
        f2 ce3 = fma2(nk, h3, e3);

        float c1l, c1h, c2lo, c2hi, c3l, c3h;
        un2(ce1, c1l, c1h); un2(ce2, c2lo, c2hi); un2(ce3, c3l, c3h);
        bool yl = stl < 0.0f, yh = sth < 0.0f;
        float x1l = __expf(yl ? c1l : coh), x1h = __expf(yh ? c1h : coh);
        float x2l = __expf(yl ? c2lo : coh), x2h = __expf(yh ? c2hi : coh);
        float x3l = __expf(yl ? c3l : coh), x3h = __expf(yh ? c3h : coh);

        // ---- B = A * V (independent of the return map above) ----
        f2 b11 = fma2(a11, v11, fma2(a12, v21, mul2(a13, v31)));
        f2 b12 = fma2(a11, v12, fma2(a12, v22, mul2(a13, v32)));
        f2 b13 = fma2(a11, v13, fma2(a12, v23, mul2(a13, v33)));
        f2 b21 = fma2(a21, v11, fma2(a22, v21, mul2(a23, v31)));
        f2 b22 = fma2(a21, v12, fma2(a22, v22, mul2(a23, v32)));
        f2 b23 = fma2(a21, v13, fma2(a22, v23, mul2(a23, v33)));
        f2 b31 = fma2(a31, v11, fma2(a32, v21, mul2(a33, v31)));
        f2 b32 = fma2(a31, v12, fma2(a32, v22, mul2(a33, v32)));
        f2 b33 = fma2(a31, v13, fma2(a32, v23, mul2(a33, v33)));

        // ---- rho_j = ||b_j||^2 ; w_j = exp(c_j) * rsqrt(rho_j)
        //      (self-normalizing: b_j/||b_j|| is exactly u_j) ----
        f2 rho1 = fma2(b11, b11, fma2(b21, b21, mul2(b31, b31)));
        f2 rho2 = fma2(b12, b12, fma2(b22, b22, mul2(b32, b32)));
        f2 rho3 = fma2(b13, b13, fma2(b23, b23, mul2(b33, b33)));

        float r1l, r1h, r2l, r2h, r3l, r3h;
        un2(rho1, r1l, r1h); un2(rho2, r2l, r2h); un2(rho3, r3l, r3h);
        f2 w1 = mk2(x1l * rsqrtf(fmaxf(r1l, 1e-30f)), x1h * rsqrtf(fmaxf(r1h, 1e-30f)));
        f2 w2 = mk2(x2l * rsqrtf(fmaxf(r2l, 1e-30f)), x2h * rsqrtf(fmaxf(r2h, 1e-30f)));
        f2 w3 = mk2(x3l * rsqrtf(fmaxf(r3l, 1e-30f)), x3h * rsqrtf(fmaxf(r3h, 1e-30f)));

        // ---- F_corrected = sum_j w_j * b_j * v_j^T ----
        f2 p11 = mul2(b11, w1), p12 = mul2(b12, w2), p13 = mul2(b13, w3);
        f2 p21 = mul2(b21, w1), p22 = mul2(b22, w2), p23 = mul2(b23, w3);
        f2 p31 = mul2(b31, w1), p32 = mul2(b32, w2), p33 = mul2(b33, w3);

        f2 o0 = fma2(p11, v11, fma2(p12, v12, mul2(p13, v13)));
        f2 o1 = fma2(p11, v21, fma2(p12, v22, mul2(p13, v23)));
        f2 o2 = fma2(p11, v31, fma2(p12, v32, mul2(p13, v33)));
        f2 o3 = fma2(p21, v11, fma2(p22, v12, mul2(p23, v13)));
        f2 o4 = fma2(p21, v21, fma2(p22, v22, mul2(p23, v23)));
        f2 o5 = fma2(p21, v31, fma2(p22, v32, mul2(p23, v33)));
        f2 o6 = fma2(p31, v11, fma2(p32, v12, mul2(p33, v13)));
        f2 o7 = fma2(p31, v21, fma2(p32, v22, mul2(p33, v23)));
        f2 o8 = fma2(p31, v31, fma2(p32, v32, mul2(p33, v33)));

        __syncthreads();   // staging buffer reuse
        float* O0 = sm + tid * 9;
        float* O1 = sm + (tid + BLOCK) * 9;
        float lo, hi;
        un2(o0, lo, hi); O0[0] = lo; O1[0] = hi;
        un2(o1, lo, hi); O0[1] = lo; O1[1] = hi;
        un2(o2, lo, hi); O0[2] = lo; O1[2] = hi;
        un2(o3, lo, hi); O0[3] = lo; O1[3] = hi;
        un2(o4, lo, hi); O0[4] = lo; O1[4] = hi;
        un2(o5, lo, hi); O0[5] = lo; O1[5] = hi;
        un2(o6, lo, hi); O0[6] = lo; O1[6] = hi;
        un2(o7, lo, hi); O0[7] = lo; O1[7] = hi;
        un2(o8, lo, hi); O0[8] = lo; O1[8] = hi;
    }
    __syncthreads();

    // ---- coalesced store: smem -> global ----
    if (cnt == MPB) {
        float4* gv = (float4*)(out + (size_t)base * 9);
        const float4* sv = (const float4*)sm;
        #pragma unroll
        for (int k = tid; k < MPB * 9 / 4; k += BLOCK) gv[k] = sv[k];
    } else {
        float* g = out + (size_t)base * 9;
        for (int k = tid; k < nflt; k += BLOCK) g[k] = sm[k];
    }
}

extern "C" void kernel_launch(void* const* d_in, const int* in_sizes, int n_in,
                              void* d_out, int out_size) {
    const float* F    = (const float*)d_in[0];
    const float* ylog = (const float*)d_in[1];
    const float* nu   = (const float*)d_in[2];
    const float* phi  = (const float*)d_in[3];
    const float* coh  = (const float*)d_in[4];
    float* out = (float*)d_out;
    int n = in_sizes[0] / 9;
    int grid = (n + MPB - 1) / MPB;
    dp_plasticity_kernel<<<grid, BLOCK>>>(F, ylog, nu, phi, coh, out, n);
}

// round 14
// speedup vs baseline: 1.0397x; 1.0397x over previous
#include <cuda_runtime.h>
#include <cuda_bf16.h>
#include <math.h>

#define DEG2RAD 0.017453292519943295f
#define LOG_SMIN -2.995732273553991f   // log(0.05)

#define BLOCK 128
#define MPB   (2 * BLOCK)   // matrices per block

typedef unsigned long long u64;
struct f2 { u64 v; };

__device__ __forceinline__ f2 mk2(float lo, float hi) {
    f2 r; asm("mov.b64 %0, {%1, %2};" : "=l"(r.v) : "f"(lo), "f"(hi)); return r;
}
__device__ __forceinline__ f2 bc2(float x) { return mk2(x, x); }
__device__ __forceinline__ void un2(f2 a, float &lo, float &hi) {
    asm("mov.b64 {%0, %1}, %2;" : "=f"(lo), "=f"(hi) : "l"(a.v));
}
__device__ __forceinline__ f2 add2(f2 a, f2 b) {
    f2 r; asm("add.rn.f32x2 %0, %1, %2;" : "=l"(r.v) : "l"(a.v), "l"(b.v)); return r;
}
__device__ __forceinline__ f2 mul2(f2 a, f2 b) {
    f2 r; asm("mul.rn.f32x2 %0, %1, %2;" : "=l"(r.v) : "l"(a.v), "l"(b.v)); return r;
}
__device__ __forceinline__ f2 fma2(f2 a, f2 b, f2 c) {
    f2 r; asm("fma.rn.f32x2 %0, %1, %2, %3;" : "=l"(r.v) : "l"(a.v), "l"(b.v), "l"(c.v)); return r;
}
__device__ __forceinline__ f2 neg2(f2 a) {
    f2 r; u64 m = 0x8000000080000000ULL;
    asm("xor.b64 %0, %1, %2;" : "=l"(r.v) : "l"(a.v), "l"(m)); return r;
}
__device__ __forceinline__ f2 abs2(f2 a) {
    f2 r; u64 m = 0x7fffffff7fffffffULL;
    asm("and.b64 %0, %1, %2;" : "=l"(r.v) : "l"(a.v), "l"(m)); return r;
}
__device__ __forceinline__ f2 sgn2(f2 a) {   // sign bits only
    f2 r; u64 m = 0x8000000080000000ULL;
    asm("and.b64 %0, %1, %2;" : "=l"(r.v) : "l"(a.v), "l"(m)); return r;
}
__device__ __forceinline__ f2 xor2(f2 a, f2 b) {
    f2 r; asm("xor.b64 %0, %1, %2;" : "=l"(r.v) : "l"(a.v), "l"(b.v)); return r;
}

// Full Jacobi step, branch-free exact rotation, NO-SWAP convention.
// Roles: s11=S_pp, s21=S_qp (annihilated, NOT written), s22=S_qq,
//        s31=S_tp, s32=S_tq. V cols (va,vb) = (p,q).
template <bool S31_ZERO>
__device__ __forceinline__ void jx(
    f2 &s11, f2 &s21, f2 &s22, f2 &s31, f2 &s32,
    f2 &va1, f2 &va2, f2 &va3,
    f2 &vb1, f2 &vb2, f2 &vb3)
{
    const f2 HALF = bc2(0.5f);
    const f2 CM1  = bc2(-1.0f);
    const f2 EPS  = bc2(1e-28f);

    f2 d  = fma2(s22, CM1, s11);
    f2 ad = abs2(d);
    f2 sg = sgn2(d);
    f2 ts = add2(s21, s21);
    f2 r2 = fma2(d, d, fma2(ts, ts, EPS));

    float r2l, r2h; un2(r2, r2l, r2h);
    f2 w = mk2(rsqrtf(r2l), rsqrtf(r2h));

    f2 c2t = mul2(ad, w);
    f2 a2  = fma2(c2t, HALF, HALF);
    float a2l, a2h; un2(a2, a2l, a2h);
    f2 ia = mk2(rsqrtf(a2l), rsqrtf(a2h));
    f2 aa = mul2(a2, ia);
    f2 bb = mul2(mul2(xor2(s21, sg), w), ia);

    // diagonal, closed form: s11' = m + sign(d)*r/2
    f2 rh  = mul2(mul2(r2, w), HALF);
    f2 rhs = xor2(rh, sg);
    f2 m   = mul2(add2(s11, s22), HALF);
    s11 = add2(m, rhs);
    s22 = add2(m, neg2(rhs));

    // third row/col rotate
    f2 nbb = neg2(bb);
    if (S31_ZERO) {
        f2 o32 = mul2(aa, s32);
        s31 = mul2(bb, s32);
        s32 = o32;
    } else {
        f2 o31 = fma2(aa, s31, mul2(bb, s32));
        f2 o32 = fma2(nbb, s31, mul2(aa, s32));
        s31 = o31; s32 = o32;
    }

    // V column rotate
    f2 t;
    t = fma2(aa, va1, mul2(bb, vb1)); vb1 = fma2(nbb, va1, mul2(aa, vb1)); va1 = t;
    t = fma2(aa, va2, mul2(bb, vb2)); vb2 = fma2(nbb, va2, mul2(aa, vb2)); va2 = t;
    t = fma2(aa, va3, mul2(bb, vb3)); vb3 = fma2(nbb, va3, mul2(aa, vb3)); va3 = t;
}

// Rotation 7 (slim): pivot (1,2), S31 known ~0. The ONLY S outputs the final
// V-only rotation reads are s22' (diagonal) and s32' (third-pair). s11'/s31'
// are dead and skipped explicitly.
__device__ __forceinline__ void jx7(
    f2 s11, f2 s21, f2 &s22, f2 &s32,
    f2 &va1, f2 &va2, f2 &va3,
    f2 &vb1, f2 &vb2, f2 &vb3)
{
    const f2 HALF = bc2(0.5f);
    const f2 CM1  = bc2(-1.0f);
    const f2 EPS  = bc2(1e-28f);

    f2 d  = fma2(s22, CM1, s11);
    f2 ad = abs2(d);
    f2 sg = sgn2(d);
    f2 ts = add2(s21, s21);
    f2 r2 = fma2(d, d, fma2(ts, ts, EPS));

    float r2l, r2h; un2(r2, r2l, r2h);
    f2 w = mk2(rsqrtf(r2l), rsqrtf(r2h));

    f2 c2t = mul2(ad, w);
    f2 a2  = fma2(c2t, HALF, HALF);
    float a2l, a2h; un2(a2, a2l, a2h);
    f2 ia = mk2(rsqrtf(a2l), rsqrtf(a2h));
    f2 aa = mul2(a2, ia);
    f2 bb = mul2(mul2(xor2(s21, sg), w), ia);

    // only the q-diagonal survives: s22' = m - sign(d)*r/2
    f2 rh  = mul2(mul2(r2, w), HALF);
    f2 rhs = xor2(rh, sg);
    f2 m   = mul2(add2(s11, s22), HALF);
    s22 = add2(m, neg2(rhs));

    // third-pair: only s32' needed (S31_ZERO path)
    s32 = mul2(aa, s32);

    // V column rotate
    f2 nbb = neg2(bb);
    f2 t;
    t = fma2(aa, va1, mul2(bb, vb1)); vb1 = fma2(nbb, va1, mul2(aa, vb1)); va1 = t;
    t = fma2(aa, va2, mul2(bb, vb2)); vb2 = fma2(nbb, va2, mul2(aa, vb2)); va2 = t;
    t = fma2(aa, va3, mul2(bb, vb3)); vb3 = fma2(nbb, va3, mul2(aa, vb3)); va3 = t;
}

// FINAL Jacobi step: V is the only live output (sigma comes from ||A v_j||),
// so skip all S updates.
__device__ __forceinline__ void jxV(
    f2 s11, f2 s21, f2 s22,
    f2 &va1, f2 &va2, f2 &va3,
    f2 &vb1, f2 &vb2, f2 &vb3)
{
    const f2 HALF = bc2(0.5f);
    const f2 CM1  = bc2(-1.0f);
    const f2 EPS  = bc2(1e-28f);

    f2 d  = fma2(s22, CM1, s11);
    f2 ad = abs2(d);
    f2 sg = sgn2(d);
    f2 ts = add2(s21, s21);
    f2 r2 = fma2(d, d, fma2(ts, ts, EPS));

    float r2l, r2h; un2(r2, r2l, r2h);
    f2 w = mk2(rsqrtf(r2l), rsqrtf(r2h));

    f2 c2t = mul2(ad, w);
    f2 a2  = fma2(c2t, HALF, HALF);
    float a2l, a2h; un2(a2, a2l, a2h);
    f2 ia = mk2(rsqrtf(a2l), rsqrtf(a2h));
    f2 aa = mul2(a2, ia);
    f2 bb = mul2(mul2(xor2(s21, sg), w), ia);
    f2 nbb = neg2(bb);

    f2 t;
    t = fma2(aa, va1, mul2(bb, vb1)); vb1 = fma2(nbb, va1, mul2(aa, vb1)); va1 = t;
    t = fma2(aa, va2, mul2(bb, vb2)); vb2 = fma2(nbb, va2, mul2(aa, vb2)); va2 = t;
    t = fma2(aa, va3, mul2(bb, vb3)); vb3 = fma2(nbb, va3, mul2(aa, vb3)); va3 = t;
}

__global__ void __launch_bounds__(BLOCK, 8)
dp_plasticity_kernel(const float* __restrict__ F,
                     const float* __restrict__ ylog_p,
                     const float* __restrict__ nu_p,
                     const float* __restrict__ phi_p,
                     const float* __restrict__ coh_p,
                     float* __restrict__ out, int n) {
    __shared__ float sm[MPB * 9];

    const int tid  = threadIdx.x;
    const int base = blockIdx.x * MPB;
    const int cnt  = min(MPB, n - base);
    const int nflt = cnt * 9;

    // ---- coalesced load: global -> smem (linear layout) ----
    if (cnt == MPB) {
        const float4* gv = (const float4*)(F + (size_t)base * 9);
        float4* sv = (float4*)sm;
        #pragma unroll
        for (int k = tid; k < MPB * 9 / 4; k += BLOCK) sv[k] = gv[k];
    } else {
        const float* g = F + (size_t)base * 9;
        for (int k = tid; k < nflt; k += BLOCK) sm[k] = g[k];
        for (int k = nflt + tid; k < MPB * 9; k += BLOCK) sm[k] = 1.0f;
    }
    __syncthreads();

    {
        const float* A0 = sm + tid * 9;
        const float* A1 = sm + (tid + BLOCK) * 9;
        f2 a11 = mk2(A0[0], A1[0]);
        f2 a12 = mk2(A0[1], A1[1]);
        f2 a13 = mk2(A0[2], A1[2]);
        f2 a21 = mk2(A0[3], A1[3]);
        f2 a22 = mk2(A0[4], A1[4]);
        f2 a23 = mk2(A0[5], A1[5]);
        f2 a31 = mk2(A0[6], A1[6]);
        f2 a32 = mk2(A0[7], A1[7]);
        f2 a33 = mk2(A0[8], A1[8]);

        // ---- S = A^T A ----
        f2 s11 = fma2(a11, a11, fma2(a21, a21, mul2(a31, a31)));
        f2 s21 = fma2(a11, a12, fma2(a21, a22, mul2(a31, a32)));
        f2 s22 = fma2(a12, a12, fma2(a22, a22, mul2(a32, a32)));
        f2 s31 = fma2(a11, a13, fma2(a21, a23, mul2(a31, a33)));
        f2 s32 = fma2(a12, a13, fma2(a22, a23, mul2(a32, a33)));
        f2 s33 = fma2(a13, a13, fma2(a23, a23, mul2(a33, a33)));

        // ---- V = I ----
        f2 v11 = bc2(1.0f), v12 = bc2(0.0f), v13 = bc2(0.0f);
        f2 v21 = bc2(0.0f), v22 = bc2(1.0f), v23 = bc2(0.0f);
        f2 v31 = bc2(0.0f), v32 = bc2(0.0f), v33 = bc2(1.0f);

        // ---- exact cyclic Jacobi, 8 rotations (7 slim, 8 V-only) ----
        jx<false>(s11, s21, s22, s31, s32, v11, v21, v31, v12, v22, v32);
        jx<true >(s22, s32, s33, s21, s31, v12, v22, v32, v13, v23, v33);
        jx<true >(s33, s31, s11, s32, s21, v13, v23, v33, v11, v21, v31);
        jx<true >(s11, s21, s22, s31, s32, v11, v21, v31, v12, v22, v32);
        jx<true >(s22, s32, s33, s21, s31, v12, v22, v32, v13, v23, v33);
        jx<true >(s33, s31, s11, s32, s21, v13, v23, v33, v11, v21, v31);
        jx7(s11, s21, s22, s32, v11, v21, v31, v12, v22, v32);
        jxV(s22, s32, s33, v12, v22, v32, v13, v23, v33);

        // ---- material params (uniform scalars) ----
        float ylog = __ldg(ylog_p);
        float nu   = __ldg(nu_p);
        float phi  = __ldg(phi_p);
        float coh  = __ldg(coh_p);
        float E = __expf(ylog);
        float sinphi = __sinf(phi * DEG2RAD);
        float alpha = sqrtf(2.0f / 3.0f) * 2.0f * sinphi / (3.0f - sinphi);
        float mu = E / (2.0f * (1.0f + nu));
        float la = E * nu / ((1.0f + nu) * (1.0f - 2.0f * nu));
        float coef = (3.0f * la + 2.0f * mu) / (2.0f * mu) * alpha;

        // ---- B = A * V ; columns b_j = sigma_j * u_j ----
        f2 b11 = fma2(a11, v11, fma2(a12, v21, mul2(a13, v31)));
        f2 b12 = fma2(a11, v12, fma2(a12, v22, mul2(a13, v32)));
        f2 b13 = fma2(a11, v13, fma2(a12, v23, mul2(a13, v33)));
        f2 b21 = fma2(a21, v11, fma2(a22, v21, mul2(a23, v31)));
        f2 b22 = fma2(a21, v12, fma2(a22, v22, mul2(a23, v32)));
        f2 b23 = fma2(a21, v13, fma2(a22, v23, mul2(a23, v33)));
        f2 b31 = fma2(a31, v11, fma2(a32, v21, mul2(a33, v31)));
        f2 b32 = fma2(a31, v12, fma2(a32, v22, mul2(a33, v32)));
        f2 b33 = fma2(a31, v13, fma2(a32, v23, mul2(a33, v33)));

        // ---- rho_j = sigma_j^2 = ||b_j||^2 ----
        f2 rho1 = fma2(b11, b11, fma2(b21, b21, mul2(b31, b31)));
        f2 rho2 = fma2(b12, b12, fma2(b22, b22, mul2(b32, b32)));
        f2 rho3 = fma2(b13, b13, fma2(b23, b23, mul2(b33, b33)));

        // ---- log-domain return map (scalar per half):
        //   lr_j = 0.5*log(rho_j); eps_j = max(lr_j, log 0.05);
        //   w_j  = exp(c_j - lr_j)  (= exp(c_j)/sigma_j, no rsqrt)
        float r1l, r1h, r2l, r2h, r3l, r3h;
        un2(rho1, r1l, r1h); un2(rho2, r2l, r2h); un2(rho3, r3l, r3h);
        float lr1l = 0.5f * __logf(fmaxf(r1l, 1e-30f));
        float lr1h = 0.5f * __logf(fmaxf(r1h, 1e-30f));
        float lr2l = 0.5f * __logf(fmaxf(r2l, 1e-30f));
        float lr2h = 0.5f * __logf(fmaxf(r2h, 1e-30f));
        float lr3l = 0.5f * __logf(fmaxf(r3l, 1e-30f));
        float lr3h = 0.5f * __logf(fmaxf(r3h, 1e-30f));
        float e1l = fmaxf(lr1l, LOG_SMIN), e1h = fmaxf(lr1h, LOG_SMIN);
        float e2l = fmaxf(lr2l, LOG_SMIN), e2h = fmaxf(lr2h, LOG_SMIN);
        float e3l = fmaxf(lr3l, LOG_SMIN), e3h = fmaxf(lr3h, LOG_SMIN);

        f2 e1 = mk2(e1l, e1h), e2 = mk2(e2l, e2h), e3 = mk2(e3l, e3h);
        f2 tr = add2(e1, add2(e2, e3));
        f2 nm = mul2(tr, bc2(-1.0f / 3.0f));
        f2 h1 = add2(e1, nm), h2 = add2(e2, nm), h3 = add2(e3, nm);
        f2 nrm2 = fma2(h1, h1, fma2(h2, h2, mul2(h3, h3)));

        float n2l, n2h; un2(nrm2, n2l, n2h);
        n2l = fmaxf(n2l, 1e-20f); n2h = fmaxf(n2h, 1e-20f);
        float rnl = rsqrtf(n2l), rnh = rsqrtf(n2h);
        float nrml = n2l * rnl, nrmh = n2h * rnh;

        f2 st = add2(tr, bc2(-3.0f * coh));
        float stl, sth; un2(st, stl, sth);
        float kl = fmaxf(nrml + coef * stl, 0.0f) * rnl;
        float kh = fmaxf(nrmh + coef * sth, 0.0f) * rnh;
        f2 nk = mk2(-kl, -kh);
        f2 ce1 = fma2(nk, h1, e1);
        f2 ce2 = fma2(nk, h2, e2);
        f2 ce3 = fma2(nk, h3, e3);

        float c1l, c1h, c2lo, c2hi, c3l, c3h;
        un2(ce1, c1l, c1h); un2(ce2, c2lo, c2hi); un2(ce3, c3l, c3h);
        bool yl = stl < 0.0f, yh = sth < 0.0f;
        f2 w1 = mk2(__expf((yl ? c1l : coh) - lr1l), __expf((yh ? c1h : coh) - lr1h));
        f2 w2 = mk2(__expf((yl ? c2lo : coh) - lr2l), __expf((yh ? c2hi : coh) - lr2h));
        f2 w3 = mk2(__expf((yl ? c3l : coh) - lr3l), __expf((yh ? c3h : coh) - lr3h));

        // ---- F_corrected = sum_j w_j * b_j * v_j^T ----
        f2 p11 = mul2(b11, w1), p12 = mul2(b12, w2), p13 = mul2(b13, w3);
        f2 p21 = mul2(b21, w1), p22 = mul2(b22, w2), p23 = mul2(b23, w3);
        f2 p31 = mul2(b31, w1), p32 = mul2(b32, w2), p33 = mul2(b33, w3);

        f2 o0 = fma2(p11, v11, fma2(p12, v12, mul2(p13, v13)));
        f2 o1 = fma2(p11, v21, fma2(p12, v22, mul2(p13, v23)));
        f2 o2 = fma2(p11, v31, fma2(p12, v32, mul2(p13, v33)));
        f2 o3 = fma2(p21, v11, fma2(p22, v12, mul2(p23, v13)));
        f2 o4 = fma2(p21, v21, fma2(p22, v22, mul2(p23, v23)));
        f2 o5 = fma2(p21, v31, fma2(p22, v32, mul2(p23, v33)));
        f2 o6 = fma2(p31, v11, fma2(p32, v12, mul2(p33, v13)));
        f2 o7 = fma2(p31, v21, fma2(p32, v22, mul2(p33, v23)));
        f2 o8 = fma2(p31, v31, fma2(p32, v32, mul2(p33, v33)));

        // NO barrier needed here: between the outer barriers, floats
        // [9*tid, 9*tid+9) and the +BLOCK partner are touched exclusively
        // by this thread (read above, written below).
        float* O0 = sm + tid * 9;
        float* O1 = sm + (tid + BLOCK) * 9;
        float lo, hi;
        un2(o0, lo, hi); O0[0] = lo; O1[0] = hi;
        un2(o1, lo, hi); O0[1] = lo; O1[1] = hi;
        un2(o2, lo, hi); O0[2] = lo; O1[2] = hi;
        un2(o3, lo, hi); O0[3] = lo; O1[3] = hi;
        un2(o4, lo, hi); O0[4] = lo; O1[4] = hi;
        un2(o5, lo, hi); O0[5] = lo; O1[5] = hi;
        un2(o6, lo, hi); O0[6] = lo; O1[6] = hi;
        un2(o7, lo, hi); O0[7] = lo; O1[7] = hi;
        un2(o8, lo, hi); O0[8] = lo; O1[8] = hi;
    }
    __syncthreads();

    // ---- coalesced store: smem -> global ----
    if (cnt == MPB) {
        float4* gv = (float4*)(out + (size_t)base * 9);
        const float4* sv = (const float4*)sm;
        #pragma unroll
        for (int k = tid; k < MPB * 9 / 4; k += BLOCK) gv[k] = sv[k];
    } else {
        float* g = out + (size_t)base * 9;
        for (int k = tid; k < nflt; k += BLOCK) g[k] = sm[k];
    }
}

extern "C" void kernel_launch(void* const* d_in, const int* in_sizes, int n_in,
                              void* d_out, int out_size) {
    const float* F    = (const float*)d_in[0];
    const float* ylog = (const float*)d_in[1];
    const float* nu   = (const float*)d_in[2];
    const float* phi  = (const float*)d_in[3];
    const float* coh  = (const float*)d_in[4];
    float* out = (float*)d_out;
    int n = in_sizes[0] / 9;
    int grid = (n + MPB - 1) / MPB;
    dp_plasticity_kernel<<<grid, BLOCK>>>(F, ylog, nu, phi, coh, out, n);
}

// round 15
// speedup vs baseline: 1.0732x; 1.0322x over previous
#include <cuda_runtime.h>
#include <cuda_bf16.h>
#include <math.h>

#define DEG2RAD 0.017453292519943295f
#define LOG_SMIN -2.995732273553991f   // log(0.05)

#define BLOCK 128
#define MPB   (2 * BLOCK)   // matrices per block

typedef unsigned long long u64;
struct f2 { u64 v; };

__device__ __forceinline__ f2 mk2(float lo, float hi) {
    f2 r; asm("mov.b64 %0, {%1, %2};" : "=l"(r.v) : "f"(lo), "f"(hi)); return r;
}
__device__ __forceinline__ f2 bc2(float x) { return mk2(x, x); }
__device__ __forceinline__ void un2(f2 a, float &lo, float &hi) {
    asm("mov.b64 {%0, %1}, %2;" : "=f"(lo), "=f"(hi) : "l"(a.v));
}
__device__ __forceinline__ f2 add2(f2 a, f2 b) {
    f2 r; asm("add.rn.f32x2 %0, %1, %2;" : "=l"(r.v) : "l"(a.v), "l"(b.v)); return r;
}
__device__ __forceinline__ f2 mul2(f2 a, f2 b) {
    f2 r; asm("mul.rn.f32x2 %0, %1, %2;" : "=l"(r.v) : "l"(a.v), "l"(b.v)); return r;
}
__device__ __forceinline__ f2 fma2(f2 a, f2 b, f2 c) {
    f2 r; asm("fma.rn.f32x2 %0, %1, %2, %3;" : "=l"(r.v) : "l"(a.v), "l"(b.v), "l"(c.v)); return r;
}
__device__ __forceinline__ f2 neg2(f2 a) {
    f2 r; u64 m = 0x8000000080000000ULL;
    asm("xor.b64 %0, %1, %2;" : "=l"(r.v) : "l"(a.v), "l"(m)); return r;
}
__device__ __forceinline__ f2 abs2(f2 a) {
    f2 r; u64 m = 0x7fffffff7fffffffULL;
    asm("and.b64 %0, %1, %2;" : "=l"(r.v) : "l"(a.v), "l"(m)); return r;
}
__device__ __forceinline__ f2 sgn2(f2 a) {   // sign bits only
    f2 r; u64 m = 0x8000000080000000ULL;
    asm("and.b64 %0, %1, %2;" : "=l"(r.v) : "l"(a.v), "l"(m)); return r;
}
__device__ __forceinline__ f2 xor2(f2 a, f2 b) {
    f2 r; asm("xor.b64 %0, %1, %2;" : "=l"(r.v) : "l"(a.v), "l"(b.v)); return r;
}

// Rotation computation + S updates ONLY (no V). Returns (aa, bb).
// Roles: s11=S_pp, s21=S_qp (annihilated, NOT written), s22=S_qq,
//        s31=S_tp, s32=S_tq.
template <bool S31_ZERO>
__device__ __forceinline__ void jxS(
    f2 &s11, f2 &s21, f2 &s22, f2 &s31, f2 &s32, f2 &aa, f2 &bb)
{
    const f2 HALF = bc2(0.5f);
    const f2 CM1  = bc2(-1.0f);
    const f2 EPS  = bc2(1e-28f);

    f2 d  = fma2(s22, CM1, s11);
    f2 ad = abs2(d);
    f2 sg = sgn2(d);
    f2 ts = add2(s21, s21);
    f2 r2 = fma2(d, d, fma2(ts, ts, EPS));

    float r2l, r2h; un2(r2, r2l, r2h);
    f2 w = mk2(rsqrtf(r2l), rsqrtf(r2h));

    f2 c2t = mul2(ad, w);
    f2 a2  = fma2(c2t, HALF, HALF);
    float a2l, a2h; un2(a2, a2l, a2h);
    f2 ia = mk2(rsqrtf(a2l), rsqrtf(a2h));
    aa = mul2(a2, ia);
    bb = mul2(mul2(xor2(s21, sg), w), ia);

    // diagonal, closed form: s11' = m + sign(d)*r/2
    f2 rh  = mul2(mul2(r2, w), HALF);
    f2 rhs = xor2(rh, sg);
    f2 m   = mul2(add2(s11, s22), HALF);
    s11 = add2(m, rhs);
    s22 = add2(m, neg2(rhs));

    // third row/col rotate
    f2 nbb = neg2(bb);
    if (S31_ZERO) {
        f2 o32 = mul2(aa, s32);
        s31 = mul2(bb, s32);
        s32 = o32;
    } else {
        f2 o31 = fma2(aa, s31, mul2(bb, s32));
        f2 o32 = fma2(nbb, s31, mul2(aa, s32));
        s31 = o31; s32 = o32;
    }
}

// Full Jacobi step (S + V). Used for rotations 4-6.
template <bool S31_ZERO>
__device__ __forceinline__ void jx(
    f2 &s11, f2 &s21, f2 &s22, f2 &s31, f2 &s32,
    f2 &va1, f2 &va2, f2 &va3,
    f2 &vb1, f2 &vb2, f2 &vb3)
{
    f2 aa, bb;
    jxS<S31_ZERO>(s11, s21, s22, s31, s32, aa, bb);
    f2 nbb = neg2(bb);
    f2 t;
    t = fma2(aa, va1, mul2(bb, vb1)); vb1 = fma2(nbb, va1, mul2(aa, vb1)); va1 = t;
    t = fma2(aa, va2, mul2(bb, vb2)); vb2 = fma2(nbb, va2, mul2(aa, vb2)); va2 = t;
    t = fma2(aa, va3, mul2(bb, vb3)); vb3 = fma2(nbb, va3, mul2(aa, vb3)); va3 = t;
}

// Rotation 7 (slim): pivot (1,2), S31 known ~0; only s22'/s32' survive.
__device__ __forceinline__ void jx7(
    f2 s11, f2 s21, f2 &s22, f2 &s32,
    f2 &va1, f2 &va2, f2 &va3,
    f2 &vb1, f2 &vb2, f2 &vb3)
{
    const f2 HALF = bc2(0.5f);
    const f2 CM1  = bc2(-1.0f);
    const f2 EPS  = bc2(1e-28f);

    f2 d  = fma2(s22, CM1, s11);
    f2 ad = abs2(d);
    f2 sg = sgn2(d);
    f2 ts = add2(s21, s21);
    f2 r2 = fma2(d, d, fma2(ts, ts, EPS));

    float r2l, r2h; un2(r2, r2l, r2h);
    f2 w = mk2(rsqrtf(r2l), rsqrtf(r2h));

    f2 c2t = mul2(ad, w);
    f2 a2  = fma2(c2t, HALF, HALF);
    float a2l, a2h; un2(a2, a2l, a2h);
    f2 ia = mk2(rsqrtf(a2l), rsqrtf(a2h));
    f2 aa = mul2(a2, ia);
    f2 bb = mul2(mul2(xor2(s21, sg), w), ia);

    f2 rh  = mul2(mul2(r2, w), HALF);
    f2 rhs = xor2(rh, sg);
    f2 m   = mul2(add2(s11, s22), HALF);
    s22 = add2(m, neg2(rhs));

    s32 = mul2(aa, s32);

    f2 nbb = neg2(bb);
    f2 t;
    t = fma2(aa, va1, mul2(bb, vb1)); vb1 = fma2(nbb, va1, mul2(aa, vb1)); va1 = t;
    t = fma2(aa, va2, mul2(bb, vb2)); vb2 = fma2(nbb, va2, mul2(aa, vb2)); va2 = t;
    t = fma2(aa, va3, mul2(bb, vb3)); vb3 = fma2(nbb, va3, mul2(aa, vb3)); va3 = t;
}

// FINAL Jacobi step: V is the only live output.
__device__ __forceinline__ void jxV(
    f2 s11, f2 s21, f2 s22,
    f2 &va1, f2 &va2, f2 &va3,
    f2 &vb1, f2 &vb2, f2 &vb3)
{
    const f2 HALF = bc2(0.5f);
    const f2 CM1  = bc2(-1.0f);
    const f2 EPS  = bc2(1e-28f);

    f2 d  = fma2(s22, CM1, s11);
    f2 ad = abs2(d);
    f2 sg = sgn2(d);
    f2 ts = add2(s21, s21);
    f2 r2 = fma2(d, d, fma2(ts, ts, EPS));

    float r2l, r2h; un2(r2, r2l, r2h);
    f2 w = mk2(rsqrtf(r2l), rsqrtf(r2h));

    f2 c2t = mul2(ad, w);
    f2 a2  = fma2(c2t, HALF, HALF);
    float a2l, a2h; un2(a2, a2l, a2h);
    f2 ia = mk2(rsqrtf(a2l), rsqrtf(a2h));
    f2 aa = mul2(a2, ia);
    f2 bb = mul2(mul2(xor2(s21, sg), w), ia);
    f2 nbb = neg2(bb);

    f2 t;
    t = fma2(aa, va1, mul2(bb, vb1)); vb1 = fma2(nbb, va1, mul2(aa, vb1)); va1 = t;
    t = fma2(aa, va2, mul2(bb, vb2)); vb2 = fma2(nbb, va2, mul2(aa, vb2)); va2 = t;
    t = fma2(aa, va3, mul2(bb, vb3)); vb3 = fma2(nbb, va3, mul2(aa, vb3)); va3 = t;
}

__global__ void __launch_bounds__(BLOCK, 8)
dp_plasticity_kernel(const float* __restrict__ F,
                     const float* __restrict__ ylog_p,
                     const float* __restrict__ nu_p,
                     const float* __restrict__ phi_p,
                     const float* __restrict__ coh_p,
                     float* __restrict__ out, int n) {
    __shared__ float sm[MPB * 9];

    const int tid  = threadIdx.x;
    const int base = blockIdx.x * MPB;
    const int cnt  = min(MPB, n - base);
    const int nflt = cnt * 9;

    // ---- coalesced load: global -> smem (linear layout) ----
    if (cnt == MPB) {
        const float4* gv = (const float4*)(F + (size_t)base * 9);
        float4* sv = (float4*)sm;
        #pragma unroll
        for (int k = tid; k < MPB * 9 / 4; k += BLOCK) sv[k] = gv[k];
    } else {
        const float* g = F + (size_t)base * 9;
        for (int k = tid; k < nflt; k += BLOCK) sm[k] = g[k];
        for (int k = nflt + tid; k < MPB * 9; k += BLOCK) sm[k] = 1.0f;
    }
    __syncthreads();

    {
        const float* A0 = sm + tid * 9;
        const float* A1 = sm + (tid + BLOCK) * 9;
        f2 a11 = mk2(A0[0], A1[0]);
        f2 a12 = mk2(A0[1], A1[1]);
        f2 a13 = mk2(A0[2], A1[2]);
        f2 a21 = mk2(A0[3], A1[3]);
        f2 a22 = mk2(A0[4], A1[4]);
        f2 a23 = mk2(A0[5], A1[5]);
        f2 a31 = mk2(A0[6], A1[6]);
        f2 a32 = mk2(A0[7], A1[7]);
        f2 a33 = mk2(A0[8], A1[8]);

        // ---- S = A^T A ----
        f2 s11 = fma2(a11, a11, fma2(a21, a21, mul2(a31, a31)));
        f2 s21 = fma2(a11, a12, fma2(a21, a22, mul2(a31, a32)));
        f2 s22 = fma2(a12, a12, fma2(a22, a22, mul2(a32, a32)));
        f2 s31 = fma2(a11, a13, fma2(a21, a23, mul2(a31, a33)));
        f2 s32 = fma2(a12, a13, fma2(a22, a23, mul2(a32, a33)));
        f2 s33 = fma2(a13, a13, fma2(a23, a23, mul2(a33, a33)));

        // ---- peeled sweep 1: V built from sparse identity structure ----
        f2 aa1, bb1, aa2, bb2, aa3, bb3;

        // rot1: pivot (1,2). V: col1=(aa1,bb1,0) col2=(-bb1,aa1,0) col3=e3
        jxS<false>(s11, s21, s22, s31, s32, aa1, bb1);
        f2 v11 = aa1;        f2 v12 = neg2(bb1);  f2 v21 = bb1;  f2 v22 = aa1;

        // rot2: pivot (2,3), cols (2,3). col3 was e3:
        //   col2' = (aa2*v12, aa2*v22, bb2) ; col3' = (-bb2*v12, -bb2*v22, aa2)
        jxS<true>(s22, s32, s33, s21, s31, aa2, bb2);
        f2 nbb2 = neg2(bb2);
        f2 v13 = mul2(nbb2, v12);
        f2 v23 = mul2(nbb2, v22);
        f2 v33 = aa2;
        v12 = mul2(aa2, v12);
        v22 = mul2(aa2, v22);
        f2 v32 = bb2;

        // rot3: pivot (3,1), cols (3,1). v31 = 0 still:
        //   col3'' = aa3*col3 + bb3*col1 ; col1'' = -bb3*col3 + aa3*col1
        jxS<true>(s33, s31, s11, s32, s21, aa3, bb3);
        f2 nbb3 = neg2(bb3);
        f2 nv13 = fma2(aa3, v13, mul2(bb3, v11));
        f2 nv23 = fma2(aa3, v23, mul2(bb3, v21));
        f2 nv33 = mul2(aa3, v33);
        f2 v31  = mul2(nbb3, v33);
        v11 = fma2(nbb3, v13, mul2(aa3, v11));
        v21 = fma2(nbb3, v23, mul2(aa3, v21));
        v13 = nv13; v23 = nv23; v33 = nv33;

        // ---- rotations 4-6 (full), 7 (slim), 8 (V-only) ----
        jx<true>(s11, s21, s22, s31, s32, v11, v21, v31, v12, v22, v32);
        jx<true>(s22, s32, s33, s21, s31, v12, v22, v32, v13, v23, v33);
        jx<true>(s33, s31, s11, s32, s21, v13, v23, v33, v11, v21, v31);
        jx7(s11, s21, s22, s32, v11, v21, v31, v12, v22, v32);
        jxV(s22, s32, s33, v12, v22, v32, v13, v23, v33);

        // ---- material params (uniform scalars) ----
        float ylog = __ldg(ylog_p);
        float nu   = __ldg(nu_p);
        float phi  = __ldg(phi_p);
        float coh  = __ldg(coh_p);
        float E = __expf(ylog);
        float sinphi = __sinf(phi * DEG2RAD);
        float alpha = sqrtf(2.0f / 3.0f) * 2.0f * sinphi / (3.0f - sinphi);
        float mu = E / (2.0f * (1.0f + nu));
        float la = E * nu / ((1.0f + nu) * (1.0f - 2.0f * nu));
        float coef = (3.0f * la + 2.0f * mu) / (2.0f * mu) * alpha;

        // ---- B = A * V ; columns b_j = sigma_j * u_j ----
        f2 b11 = fma2(a11, v11, fma2(a12, v21, mul2(a13, v31)));
        f2 b12 = fma2(a11, v12, fma2(a12, v22, mul2(a13, v32)));
        f2 b13 = fma2(a11, v13, fma2(a12, v23, mul2(a13, v33)));
        f2 b21 = fma2(a21, v11, fma2(a22, v21, mul2(a23, v31)));
        f2 b22 = fma2(a21, v12, fma2(a22, v22, mul2(a23, v32)));
        f2 b23 = fma2(a21, v13, fma2(a22, v23, mul2(a23, v33)));
        f2 b31 = fma2(a31, v11, fma2(a32, v21, mul2(a33, v31)));
        f2 b32 = fma2(a31, v12, fma2(a32, v22, mul2(a33, v32)));
        f2 b33 = fma2(a31, v13, fma2(a32, v23, mul2(a33, v33)));

        // ---- rho_j = sigma_j^2 = ||b_j||^2 ----
        f2 rho1 = fma2(b11, b11, fma2(b21, b21, mul2(b31, b31)));
        f2 rho2 = fma2(b12, b12, fma2(b22, b22, mul2(b32, b32)));
        f2 rho3 = fma2(b13, b13, fma2(b23, b23, mul2(b33, b33)));

        // ---- log-domain return map (scalar per half) ----
        float r1l, r1h, r2l, r2h, r3l, r3h;
        un2(rho1, r1l, r1h); un2(rho2, r2l, r2h); un2(rho3, r3l, r3h);
        float lr1l = 0.5f * __logf(fmaxf(r1l, 1e-30f));
        float lr1h = 0.5f * __logf(fmaxf(r1h, 1e-30f));
        float lr2l = 0.5f * __logf(fmaxf(r2l, 1e-30f));
        float lr2h = 0.5f * __logf(fmaxf(r2h, 1e-30f));
        float lr3l = 0.5f * __logf(fmaxf(r3l, 1e-30f));
        float lr3h = 0.5f * __logf(fmaxf(r3h, 1e-30f));
        float e1l = fmaxf(lr1l, LOG_SMIN), e1h = fmaxf(lr1h, LOG_SMIN);
        float e2l = fmaxf(lr2l, LOG_SMIN), e2h = fmaxf(lr2h, LOG_SMIN);
        float e3l = fmaxf(lr3l, LOG_SMIN), e3h = fmaxf(lr3h, LOG_SMIN);

        f2 e1 = mk2(e1l, e1h), e2 = mk2(e2l, e2h), e3 = mk2(e3l, e3h);
        f2 tr = add2(e1, add2(e2, e3));
        f2 nm = mul2(tr, bc2(-1.0f / 3.0f));
        f2 h1 = add2(e1, nm), h2 = add2(e2, nm), h3 = add2(e3, nm);
        f2 nrm2 = fma2(h1, h1, fma2(h2, h2, mul2(h3, h3)));

        float n2l, n2h; un2(nrm2, n2l, n2h);
        n2l = fmaxf(n2l, 1e-20f); n2h = fmaxf(n2h, 1e-20f);
        float rnl = rsqrtf(n2l), rnh = rsqrtf(n2h);
        float nrml = n2l * rnl, nrmh = n2h * rnh;

        f2 st = add2(tr, bc2(-3.0f * coh));
        float stl, sth; un2(st, stl, sth);
        float kl = fmaxf(nrml + coef * stl, 0.0f) * rnl;
        float kh = fmaxf(nrmh + coef * sth, 0.0f) * rnh;
        f2 nk = mk2(-kl, -kh);
        f2 ce1 = fma2(nk, h1, e1);
        f2 ce2 = fma2(nk, h2, e2);
        f2 ce3 = fma2(nk, h3, e3);

        float c1l, c1h, c2lo, c2hi, c3l, c3h;
        un2(ce1, c1l, c1h); un2(ce2, c2lo, c2hi); un2(ce3, c3l, c3h);
        bool yl = stl < 0.0f, yh = sth < 0.0f;
        f2 w1 = mk2(__expf((yl ? c1l : coh) - lr1l), __expf((yh ? c1h : coh) - lr1h));
        f2 w2 = mk2(__expf((yl ? c2lo : coh) - lr2l), __expf((yh ? c2hi : coh) - lr2h));
        f2 w3 = mk2(__expf((yl ? c3l : coh) - lr3l), __expf((yh ? c3h : coh) - lr3h));

        // ---- F_corrected = sum_j w_j * b_j * v_j^T ----
        f2 p11 = mul2(b11, w1), p12 = mul2(b12, w2), p13 = mul2(b13, w3);
        f2 p21 = mul2(b21, w1), p22 = mul2(b22, w2), p23 = mul2(b23, w3);
        f2 p31 = mul2(b31, w1), p32 = mul2(b32, w2), p33 = mul2(b33, w3);

        f2 o0 = fma2(p11, v11, fma2(p12, v12, mul2(p13, v13)));
        f2 o1 = fma2(p11, v21, fma2(p12, v22, mul2(p13, v23)));
        f2 o2 = fma2(p11, v31, fma2(p12, v32, mul2(p13, v33)));
        f2 o3 = fma2(p21, v11, fma2(p22, v12, mul2(p23, v13)));
        f2 o4 = fma2(p21, v21, fma2(p22, v22, mul2(p23, v23)));
        f2 o5 = fma2(p21, v31, fma2(p22, v32, mul2(p23, v33)));
        f2 o6 = fma2(p31, v11, fma2(p32, v12, mul2(p33, v13)));
        f2 o7 = fma2(p31, v21, fma2(p32, v22, mul2(p33, v23)));
        f2 o8 = fma2(p31, v31, fma2(p32, v32, mul2(p33, v33)));

        // NO barrier needed here: these smem slots are private to this thread
        // between the outer barriers.
        float* O0 = sm + tid * 9;
        float* O1 = sm + (tid + BLOCK) * 9;
        float lo, hi;
        un2(o0, lo, hi); O0[0] = lo; O1[0] = hi;
        un2(o1, lo, hi); O0[1] = lo; O1[1] = hi;
        un2(o2, lo, hi); O0[2] = lo; O1[2] = hi;
        un2(o3, lo, hi); O0[3] = lo; O1[3] = hi;
        un2(o4, lo, hi); O0[4] = lo; O1[4] = hi;
        un2(o5, lo, hi); O0[5] = lo; O1[5] = hi;
        un2(o6, lo, hi); O0[6] = lo; O1[6] = hi;
        un2(o7, lo, hi); O0[7] = lo; O1[7] = hi;
        un2(o8, lo, hi); O0[8] = lo; O1[8] = hi;
    }
    __syncthreads();

    // ---- coalesced store: smem -> global ----
    if (cnt == MPB) {
        float4* gv = (float4*)(out + (size_t)base * 9);
        const float4* sv = (const float4*)sm;
        #pragma unroll
        for (int k = tid; k < MPB * 9 / 4; k += BLOCK) gv[k] = sv[k];
    } else {
        float* g = out + (size_t)base * 9;
        for (int k = tid; k < nflt; k += BLOCK) g[k] = sm[k];
    }
}

extern "C" void kernel_launch(void* const* d_in, const int* in_sizes, int n_in,
                              void* d_out, int out_size) {
    const float* F    = (const float*)d_in[0];
    const float* ylog = (const float*)d_in[1];
    const float* nu   = (const float*)d_in[2];
    const float* phi  = (const float*)d_in[3];
    const float* coh  = (const float*)d_in[4];
    float* out = (float*)d_out;
    int n = in_sizes[0] / 9;
    int grid = (n + MPB - 1) / MPB;
    dp_plasticity_kernel<<<grid, BLOCK>>>(F, ylog, nu, phi, coh, out, n);
}